// round 1
// baseline (speedup 1.0000x reference)
#include <cuda_runtime.h>
#include <math.h>

// Problem constants
#define B_   8
#define T_   4
#define C_   512
#define H_   32
#define W_   32
#define HW_  1024
#define BT_  32          // B_*T_
#define TC_  2048        // T_*C_
#define KSPLIT 8
#define CPB  (C_/KSPLIT) // 64 channels per block
#define HP_  28
#define WP_  28
#define NP_  784         // 28*28
#define BN_EPS 1e-5

// Scratch (allocation-free rule: __device__ globals)
__device__ float g_A[TC_];
__device__ float g_B[TC_];
__device__ float g_D[TC_];
__device__ float g_part[KSPLIT][BT_ * HW_];

// ---------------------------------------------------------------------------
// Kernel 1: per-(t,c) stats for left and right -> A, B, D coefficients
// grid: 2048 blocks (tc), 256 threads; each thread loads 8 b's x float4
// ---------------------------------------------------------------------------
__global__ __launch_bounds__(256) void stats_kernel(
    const float* __restrict__ l, const float* __restrict__ r,
    const float* __restrict__ gamma)
{
    const int tc  = blockIdx.x;      // t*C + c
    const int t   = tc / C_;
    const int c   = tc % C_;
    const int tid = threadIdx.x;
    const int hw  = tid * 4;

    float sl = 0.f, ql = 0.f, sr = 0.f, qr = 0.f;
    #pragma unroll
    for (int b = 0; b < B_; b++) {
        size_t off = ((size_t)((b * T_ + t) * C_ + c)) * HW_ + hw;
        float4 lv = *reinterpret_cast<const float4*>(l + off);
        float4 rv = *reinterpret_cast<const float4*>(r + off);
        sl += lv.x + lv.y + lv.z + lv.w;
        ql += lv.x*lv.x + lv.y*lv.y + lv.z*lv.z + lv.w*lv.w;
        sr += rv.x + rv.y + rv.z + rv.w;
        qr += rv.x*rv.x + rv.y*rv.y + rv.z*rv.z + rv.w*rv.w;
    }

    __shared__ double s0[256], s1[256], s2[256], s3[256];
    s0[tid] = (double)sl; s1[tid] = (double)ql;
    s2[tid] = (double)sr; s3[tid] = (double)qr;
    __syncthreads();
    for (int st = 128; st > 0; st >>= 1) {
        if (tid < st) {
            s0[tid] += s0[tid + st];
            s1[tid] += s1[tid + st];
            s2[tid] += s2[tid + st];
            s3[tid] += s3[tid + st];
        }
        __syncthreads();
    }

    if (tid == 0) {
        const double n = (double)(B_ * HW_);   // 8192
        double mul = s0[0] / n;
        double mur = s2[0] / n;
        double varl = s1[0] / n - mul * mul;
        double varr = s3[0] / n - mur * mur;
        double invl = 1.0 / sqrt(varl + BN_EPS);
        double invr = 1.0 / sqrt(varr + BN_EPS);
        double g = (double)gamma[c];
        double A = g * invl;
        double Bc = g * invr;
        g_A[tc] = (float)A;
        g_B[tc] = (float)Bc;
        g_D[tc] = (float)(A * mul - Bc * mur);
    }
}

// ---------------------------------------------------------------------------
// Kernel 2: diff2 partials. grid: 32 (b,t) x 8 channel-splits, 1024 threads.
// Each thread owns one spatial position, loops 64 channels. Fully coalesced.
// ---------------------------------------------------------------------------
__global__ __launch_bounds__(1024) void diff2_kernel(
    const float* __restrict__ l, const float* __restrict__ r)
{
    const int bt   = blockIdx.x / KSPLIT;   // b*T + t
    const int part = blockIdx.x % KSPLIT;
    const int hw   = threadIdx.x;           // 0..1023
    const int t    = bt % T_;

    __shared__ float sA[CPB], sB[CPB], sD[CPB];
    if (hw < CPB) {
        int tc = t * C_ + part * CPB + hw;
        sA[hw] = g_A[tc];
        sB[hw] = g_B[tc];
        sD[hw] = g_D[tc];
    }
    __syncthreads();

    const float* lp = l + ((size_t)(bt * C_ + part * CPB)) * HW_ + hw;
    const float* rp = r + ((size_t)(bt * C_ + part * CPB)) * HW_ + hw;

    float acc = 0.f;
    #pragma unroll 4
    for (int i = 0; i < CPB; i++) {
        float d = sA[i] * lp[(size_t)i * HW_] - sB[i] * rp[(size_t)i * HW_] - sD[i];
        acc = fmaf(d, d, acc);
    }
    g_part[part][bt * HW_ + hw] = acc;
}

// ---------------------------------------------------------------------------
// Kernel 3: sum partials, 5x5 window sum, sqrt, max + first-argmin.
// grid: 32 blocks (one per (b,t)), 1024 threads.
// Output layout (all float32, tuple order, row-major flattened):
//   [0,32)         asymmetry_values   (B,T)
//   [32,96)        asymmetry_coords   (B,T,2) as floats, [x, y]
//   [96,25184)     heatmap            (B,T,28,28)
// ---------------------------------------------------------------------------
__global__ __launch_bounds__(1024) void finalize_kernel(float* __restrict__ out)
{
    const int bt  = blockIdx.x;
    const int tid = threadIdx.x;

    __shared__ float d2[HW_];
    {
        float s = 0.f;
        #pragma unroll
        for (int k = 0; k < KSPLIT; k++) s += g_part[k][bt * HW_ + tid];
        d2[tid] = s;
    }
    __syncthreads();

    float mymax = -3.0e38f;
    float mymin =  3.0e38f;
    int   myidx = 0x7fffffff;

    if (tid < NP_) {
        const int y = tid / WP_;
        const int x = tid % WP_;
        float ws = 0.f;
        #pragma unroll
        for (int dy = 0; dy < 5; dy++) {
            #pragma unroll
            for (int dx = 0; dx < 5; dx++) {
                ws += d2[(y + dy) * W_ + (x + dx)];
            }
        }
        float hm = sqrtf(ws / 25.0f);
        out[96 + bt * NP_ + tid] = hm;
        mymax = hm;
        mymin = hm;
        myidx = tid;
    }

    __shared__ float smx[1024];
    __shared__ float smn[1024];
    __shared__ int   six[1024];
    smx[tid] = mymax; smn[tid] = mymin; six[tid] = myidx;
    __syncthreads();
    for (int st = 512; st > 0; st >>= 1) {
        if (tid < st) {
            smx[tid] = fmaxf(smx[tid], smx[tid + st]);
            float v = smn[tid + st];
            int  ix = six[tid + st];
            // first-occurrence argmin (JAX semantics): strictly smaller value,
            // or equal value with smaller index
            if (v < smn[tid] || (v == smn[tid] && ix < six[tid])) {
                smn[tid] = v; six[tid] = ix;
            }
        }
        __syncthreads();
    }

    if (tid == 0) {
        out[bt] = smx[0];
        int idx = six[0];
        out[32 + bt * 2 + 0] = (float)(idx % WP_);  // x_argmin
        out[32 + bt * 2 + 1] = (float)(idx / WP_);  // y_argmin
    }
}

// ---------------------------------------------------------------------------
extern "C" void kernel_launch(void* const* d_in, const int* in_sizes, int n_in,
                              void* d_out, int out_size)
{
    const float* l     = (const float*)d_in[0];
    const float* r     = (const float*)d_in[1];
    const float* gamma = (const float*)d_in[2];
    // d_in[3] = bn_beta: cancels exactly in (l_bn - r_bn), unused.
    float* out = (float*)d_out;

    stats_kernel<<<TC_, 256>>>(l, r, gamma);
    diff2_kernel<<<BT_ * KSPLIT, 1024>>>(l, r);
    finalize_kernel<<<BT_, 1024>>>(out);
}